// round 13
// baseline (speedup 1.0000x reference)
#include <cuda_runtime.h>
#include <stdint.h>

// Inputs (metadata order):
//  0: vertex_dofs  [V,1]  f32
//  1: edge_dofs    [E,2]  f32
//  2: face_dofs    [C,1]  f32
//  3: y            [C,10,16] f32
//  4: faces        [C,3]  i32
//  5: faces_to_edges [C,3] i32
//  6: edge_orientation [C,3] i32
// Output: [C,16] f32

#define NB 10
#define QPTS 16
#define THREADS 64   // 8 threads per cell now; 2-warp blocks (best measured)

__global__ __launch_bounds__(THREADS)
void quadfn_kernel(const float* __restrict__ vertex_dofs,
                   const float* __restrict__ edge_dofs,
                   const float* __restrict__ face_dofs,
                   const float* __restrict__ y,
                   const int*   __restrict__ faces,
                   const int*   __restrict__ f2e,
                   const int*   __restrict__ orient,
                   float*       __restrict__ out,
                   int C)
{
    const int tid  = blockIdx.x * THREADS + threadIdx.x;
    const int c    = tid >> 3;          // one cell per 8-lane group
    const int j    = threadIdx.x & 7;   // lane within group
    const int qg   = j & 3;             // which float4 of Q=16
    const int bh   = j >> 2;            // basis half: 0 = even b, 1 = odd b
    const unsigned m = 0xffffffffu;
    const bool act = (c < C);           // no divergent exit: full-mask shuffles

    // ---- Phase 0: y tile. 5 LDG.128 per thread; each warp-wide instruction
    // now covers 4 FULL 128B lines (8 lanes x 16B contiguous per cell), i.e.
    // one wavefront per line instead of two -> 2x fewer L1tex wavefronts
    // per cell than the 4-lane layout. __ldcs = evict-first (zero reuse).
    float4 v[5];
    if (act) {
        const float4* yv = reinterpret_cast<const float4*>(y)
                           + (size_t)c * (NB * QPTS / 4) + j;
        #pragma unroll
        for (int i = 0; i < 5; i++)
            v[i] = __ldcs(yv + i * 8);      // float4 idx c*40 + 8i + j
    } else {
        #pragma unroll
        for (int i = 0; i < 5; i++) v[i] = make_float4(0.f, 0.f, 0.f, 0.f);
    }

    // ---- Phase 1: gather. Vertex chain on lanes 0-2 and edge chain on
    // lanes 4-6 run in PARALLEL on different lanes; face dof on lane 3.
    float wv = 0.f, wa = 0.f, wb = 0.f, wf = 0.f;
    if (act) {
        if (j < 3) {
            int vidx = __ldg(&faces[3 * c + j]);
            wv = __ldg(&vertex_dofs[vidx]);
        } else if (j == 3) {
            wf = __ldg(&face_dofs[c]);
        } else if (j < 7) {
            int e    = j - 4;
            int eidx = __ldg(&f2e[3 * c + e]);
            int o    = __ldg(&orient[3 * c + e]);
            float2 ed = __ldg((const float2*)edge_dofs + eidx);
            wa = (o != 0) ? ed.x : ed.y;   // first edge dof
            wb = (o != 0) ? ed.y : ed.x;   // second edge dof
        }
    }

    // ---- Phase 2: broadcast the 10 weights within the 8-lane group.
    float w0 = __shfl_sync(m, wv, 0, 8);
    float w1 = __shfl_sync(m, wv, 1, 8);
    float w2 = __shfl_sync(m, wv, 2, 8);
    float w3 = __shfl_sync(m, wa, 4, 8);
    float w4 = __shfl_sync(m, wb, 4, 8);
    float w5 = __shfl_sync(m, wa, 5, 8);
    float w6 = __shfl_sync(m, wb, 5, 8);
    float w7 = __shfl_sync(m, wa, 6, 8);
    float w8 = __shfl_sync(m, wb, 6, 8);
    float w9 = __shfl_sync(m, wf, 3, 8);

    // This thread handles bases {2i + bh}: select its 5 weights.
    float u0 = bh ? w1 : w0;
    float u1 = bh ? w3 : w2;
    float u2 = bh ? w5 : w4;
    float u3 = bh ? w7 : w6;
    float u4 = bh ? w9 : w8;

    // ---- Phase 3: half-contraction on the prefetched registers.
    float4 acc;
    acc.x = u0 * v[0].x; acc.y = u0 * v[0].y;
    acc.z = u0 * v[0].z; acc.w = u0 * v[0].w;
    #define ACC(W, B)                         \
        acc.x = fmaf(W, v[B].x, acc.x);       \
        acc.y = fmaf(W, v[B].y, acc.y);       \
        acc.z = fmaf(W, v[B].z, acc.z);       \
        acc.w = fmaf(W, v[B].w, acc.w);
    ACC(u1, 1) ACC(u2, 2) ACC(u3, 3) ACC(u4, 4)
    #undef ACC

    // ---- Phase 4: combine even/odd halves (partner lane j ^ 4, same qg).
    acc.x += __shfl_xor_sync(m, acc.x, 4);
    acc.y += __shfl_xor_sync(m, acc.y, 4);
    acc.z += __shfl_xor_sync(m, acc.z, 4);
    acc.w += __shfl_xor_sync(m, acc.w, 4);

    if (act && bh == 0)
        __stcs(reinterpret_cast<float4*>(out + (size_t)c * QPTS) + qg, acc);
}

extern "C" void kernel_launch(void* const* d_in, const int* in_sizes, int n_in,
                              void* d_out, int out_size)
{
    const float* vertex_dofs = (const float*)d_in[0];
    const float* edge_dofs   = (const float*)d_in[1];
    const float* face_dofs   = (const float*)d_in[2];
    const float* y           = (const float*)d_in[3];
    const int*   faces       = (const int*)d_in[4];
    const int*   f2e         = (const int*)d_in[5];
    const int*   orient      = (const int*)d_in[6];
    float*       out         = (float*)d_out;

    // Derive C from y: [C, NB, Q]
    int C = in_sizes[3] / (NB * QPTS);

    long long total_threads = (long long)C * 8;
    int blocks = (int)((total_threads + THREADS - 1) / THREADS);
    quadfn_kernel<<<blocks, THREADS>>>(vertex_dofs, edge_dofs, face_dofs, y,
                                       faces, f2e, orient, out, C);
}

// round 14
// speedup vs baseline: 1.1861x; 1.1861x over previous
#include <cuda_runtime.h>
#include <stdint.h>

// Inputs (metadata order):
//  0: vertex_dofs  [V,1]  f32
//  1: edge_dofs    [E,2]  f32
//  2: face_dofs    [C,1]  f32
//  3: y            [C,10,16] f32
//  4: faces        [C,3]  i32
//  5: faces_to_edges [C,3] i32
//  6: edge_orientation [C,3] i32
// Output: [C,16] f32

#define NB 10
#define QPTS 16
#define THREADS 32   // 4 threads per cell; single-warp blocks = finest
                     // block-start granularity (256->128->64 monotone wins)

__global__ __launch_bounds__(THREADS)
void quadfn_kernel(const float* __restrict__ vertex_dofs,
                   const float* __restrict__ edge_dofs,
                   const float* __restrict__ face_dofs,
                   const float* __restrict__ y,
                   const int*   __restrict__ faces,
                   const int*   __restrict__ f2e,
                   const int*   __restrict__ orient,
                   float*       __restrict__ out,
                   int C)
{
    const int tid  = blockIdx.x * THREADS + threadIdx.x;
    const int c    = tid >> 2;          // one cell per 4-lane group
    const int lane = threadIdx.x & 31;
    const int qg   = lane & 3;          // which float4 of Q=16
    const int grp  = lane & ~3;         // group base lane within warp

    if (c >= C) return;                 // tail: whole 4-lane groups drop out

    // ---- Phase 0: streaming y tile first (measured-fastest ordering).
    // 10 independent LDG.128 in flight across the gather chain.
    // __ldcs = evict-first: y has zero reuse; keep L2 for the dof tables.
    float4 v[NB];
    {
        const float4* yv = reinterpret_cast<const float4*>(
                               y + (size_t)c * NB * QPTS) + qg;
        #pragma unroll
        for (int b = 0; b < NB; b++)
            v[b] = __ldcs(yv + b * (QPTS / 4));
    }

    // ---- Phase 1: cooperative gather within the 4-lane group (no smem,
    // no __syncthreads — warps stay fully independent).
    float wv = 0.f, wa = 0.f, wb = 0.f, wf = 0.f;
    if (qg < 3) {
        int vidx = __ldg(&faces[3 * c + qg]);
        wv = __ldg(&vertex_dofs[vidx]);
        int    eidx = __ldg(&f2e[3 * c + qg]);
        int    o    = __ldg(&orient[3 * c + qg]);
        float2 ed   = __ldg((const float2*)edge_dofs + eidx);
        wa = (o != 0) ? ed.x : ed.y;   // first edge dof
        wb = (o != 0) ? ed.y : ed.x;   // second edge dof
    } else {
        wf = __ldg(&face_dofs[c]);
    }

    // ---- Phase 2: broadcast the 10 weights across the group via shuffle.
    const unsigned m = 0xffffffffu;
    float w0 = __shfl_sync(m, wv, grp + 0);
    float w1 = __shfl_sync(m, wv, grp + 1);
    float w2 = __shfl_sync(m, wv, grp + 2);
    float w3 = __shfl_sync(m, wa, grp + 0);
    float w4 = __shfl_sync(m, wb, grp + 0);
    float w5 = __shfl_sync(m, wa, grp + 1);
    float w6 = __shfl_sync(m, wb, grp + 1);
    float w7 = __shfl_sync(m, wa, grp + 2);
    float w8 = __shfl_sync(m, wb, grp + 2);
    float w9 = __shfl_sync(m, wf, grp + 3);

    // ---- Phase 3: contraction on the prefetched registers ----
    float4 acc;
    acc.x = w0 * v[0].x; acc.y = w0 * v[0].y;
    acc.z = w0 * v[0].z; acc.w = w0 * v[0].w;

    #define ACC(W, B)                         \
        acc.x = fmaf(W, v[B].x, acc.x);       \
        acc.y = fmaf(W, v[B].y, acc.y);       \
        acc.z = fmaf(W, v[B].z, acc.z);       \
        acc.w = fmaf(W, v[B].w, acc.w);
    ACC(w1, 1) ACC(w2, 2) ACC(w3, 3) ACC(w4, 4)
    ACC(w5, 5) ACC(w6, 6) ACC(w7, 7) ACC(w8, 8) ACC(w9, 9)
    #undef ACC

    __stcs(reinterpret_cast<float4*>(out + (size_t)c * QPTS) + qg, acc);
}

extern "C" void kernel_launch(void* const* d_in, const int* in_sizes, int n_in,
                              void* d_out, int out_size)
{
    const float* vertex_dofs = (const float*)d_in[0];
    const float* edge_dofs   = (const float*)d_in[1];
    const float* face_dofs   = (const float*)d_in[2];
    const float* y           = (const float*)d_in[3];
    const int*   faces       = (const int*)d_in[4];
    const int*   f2e         = (const int*)d_in[5];
    const int*   orient      = (const int*)d_in[6];
    float*       out         = (float*)d_out;

    // Derive C from y: [C, NB, Q]
    int C = in_sizes[3] / (NB * QPTS);

    long long total_threads = (long long)C * 4;
    int blocks = (int)((total_threads + THREADS - 1) / THREADS);
    quadfn_kernel<<<blocks, THREADS>>>(vertex_dofs, edge_dofs, face_dofs, y,
                                       faces, f2e, orient, out, C);
}